// round 5
// baseline (speedup 1.0000x reference)
#include <cuda_runtime.h>
#include <cstdint>

#define D         32000
#define D4        (D / 4)            // 8000 float4 per row
#define ROW_BYTES (D * 4)            // 128000 bytes
#define THREADS   1024
#define NV4       8
#define NE        32
#define MAX_ITER  100
#define TOL       1e-5f
#define HI_OFFSET 1.9888196601125011f   // -gp(1/32000) = 2 - 2/sqrt(32000)
#define NEG_BIG   -1e30f
#define ROWS      4096
#define ACT_CAP   2048

__device__ __forceinline__ uint32_t smem_u32(const void* p) {
    uint32_t a;
    asm("{ .reg .u64 t; cvta.to.shared.u64 t, %1; cvt.u32.u64 %0, t; }"
        : "=r"(a) : "l"(p));
    return a;
}

__device__ __forceinline__ void mbar_init(uint32_t mbar, uint32_t count) {
    asm volatile("mbarrier.init.shared.b64 [%0], %1;" :: "r"(mbar), "r"(count) : "memory");
}

__device__ __forceinline__ void tma_prefetch_row(uint32_t dst_smem, const float* src,
                                                 uint32_t mbar) {
    asm volatile("mbarrier.arrive.expect_tx.shared.b64 _, [%0], %1;"
                 :: "r"(mbar), "r"((uint32_t)ROW_BYTES) : "memory");
    asm volatile("cp.async.bulk.shared::cta.global.mbarrier::complete_tx::bytes "
                 "[%0], [%1], %2, [%3];"
                 :: "r"(dst_smem), "l"(src), "r"((uint32_t)ROW_BYTES), "r"(mbar)
                 : "memory");
}

__device__ __forceinline__ void mbar_wait(uint32_t mbar, uint32_t phase) {
    asm volatile(
        "{\n\t"
        ".reg .pred P;\n\t"
        "W%=:\n\t"
        "mbarrier.try_wait.parity.acquire.cta.shared::cta.b64 P, [%0], %1, 0x989680;\n\t"
        "@!P bra W%=;\n\t"
        "}"
        :: "r"(mbar), "r"(phase) : "memory");
}

__device__ __forceinline__ float warp_sum(float v) {
#pragma unroll
    for (int o = 16; o; o >>= 1) v += __shfl_xor_sync(0xffffffffu, v, o);
    return v;
}

__device__ __forceinline__ float warp_max(float v) {
#pragma unroll
    for (int o = 16; o; o >>= 1) v = fmaxf(v, __shfl_xor_sync(0xffffffffu, v, o));
    return v;
}

__global__ void __launch_bounds__(THREADS, 1)
tsallis_secant_kernel(const float* __restrict__ X, float* __restrict__ Y) {
    extern __shared__ float buf[];          // D floats: TMA staging buffer
    __shared__ float act[ACT_CAP];          // compacted active elements (index order)
    __shared__ float red[2][32];            // double-buffered reduction scratch
    __shared__ int   iscan[32];
    __shared__ int   n_act_s;
    __shared__ float tau_s;
    __shared__ int   fb_s;
    __shared__ __align__(8) uint64_t mbar_storage;

    const int tid  = threadIdx.x;
    const int lane = tid & 31;
    const int wid  = tid >> 5;

    const uint32_t mbar    = smem_u32(&mbar_storage);
    const uint32_t buf_u32 = smem_u32(buf);

    if (tid == 0) mbar_init(mbar, 1);
    __syncthreads();

    int rb = 0;  // reduction buffer toggle (uniform)

    auto block_sum = [&](float s) -> float {
        s = warp_sum(s);
        if (lane == 0) red[rb][wid] = s;
        __syncthreads();
        float t = warp_sum(red[rb][lane]);
        rb ^= 1;
        return t;
    };

    int row = blockIdx.x;
    const int stride = gridDim.x;

    if (tid == 0 && row < ROWS) {
        tma_prefetch_row(buf_u32, X + (size_t)row * D, mbar);
    }
    uint32_t phase = 0;

    for (; row < ROWS; row += stride) {
        mbar_wait(mbar, phase);
        phase ^= 1;

        // ---- SMEM -> registers, fused local max ----
        float xv[NE];
        float m = NEG_BIG;
        const float4* b4 = reinterpret_cast<const float4*>(buf);
#pragma unroll
        for (int k = 0; k < NV4; k++) {
            const int i4 = tid + k * THREADS;
            if (k < NV4 - 1 || i4 < D4) {
                float4 v = b4[i4];
                xv[4 * k + 0] = v.x;
                xv[4 * k + 1] = v.y;
                xv[4 * k + 2] = v.z;
                xv[4 * k + 3] = v.w;
            } else {
                xv[4 * k + 0] = NEG_BIG;
                xv[4 * k + 1] = NEG_BIG;
                xv[4 * k + 2] = NEG_BIG;
                xv[4 * k + 3] = NEG_BIG;
            }
        }
#pragma unroll
        for (int k = 0; k < NE; k++) m = fmaxf(m, xv[k]);

        __syncthreads();   // all threads done reading buf

        // ---- kick prefetch of next row (overlaps everything below) ----
        const int nrow = row + stride;
        if (tid == 0 && nrow < ROWS) {
            tma_prefetch_row(buf_u32, X + (size_t)nrow * D, mbar);
        }

        // ---- block max (one-sync) ----
        m = warp_max(m);
        if (lane == 0) red[rb][wid] = m;
        __syncthreads();
        const float max_val = warp_max(red[rb][lane]);
        rb ^= 1;

        // ---- deterministic index-ordered compaction of {x > max-2} ----
        const float thr = max_val - 2.0f;
        int cnt = 0;
#pragma unroll
        for (int k = 0; k < NE; k++) cnt += (xv[k] > thr) ? 1 : 0;

        int inc = cnt;
#pragma unroll
        for (int o = 1; o < 32; o <<= 1) {
            int n = __shfl_up_sync(0xffffffffu, inc, o);
            if (lane >= o) inc += n;
        }
        if (lane == 31) iscan[wid] = inc;
        __syncthreads();
        if (wid == 0) {
            int v = iscan[lane];
            int iv = v;
#pragma unroll
            for (int o = 1; o < 32; o <<= 1) {
                int n = __shfl_up_sync(0xffffffffu, iv, o);
                if (lane >= o) iv += n;
            }
            iscan[lane] = iv - v;            // exclusive warp base
            if (lane == 31) n_act_s = iv;    // total
        }
        __syncthreads();
        {
            int pos = iscan[wid] + (inc - cnt);
#pragma unroll
            for (int k = 0; k < NE; k++) {
                if (xv[k] > thr) {
                    if (pos < ACT_CAP) act[pos] = xv[k];
                    pos++;
                }
            }
        }
        __syncthreads();
        const int n_act = n_act_s;

        const float lo0 = max_val;                 // gp(1.0) = 0
        const float hi0 = max_val + HI_OFFSET;

        // ---- warp-0-only secant over the compacted set: NO block barriers ----
        if (wid == 0) {
            int fb = 0;
            float hi = hi0;
            if (n_act <= ACT_CAP) {
                // fused initial dual eval (lo0, hi0 >= max_val: identity exact)
                const float cl = fmaf(lo0, -0.5f, 1.0f);
                const float ch = fmaf(hi0, -0.5f, 1.0f);
                float a = 0.0f, b = 0.0f;
                for (int i = lane; i < n_act; i += 32) {
                    float x = act[i];
                    float v = fmaxf(fmaf(x, 0.5f, cl), 0.0f);
                    float w = fmaxf(fmaf(x, 0.5f, ch), 0.0f);
                    a = fmaf(v, v, a);
                    b = fmaf(w, w, b);
                }
                float f_lo = warp_sum(a) - 1.0f;
                float f_hi = warp_sum(b) - 1.0f;
                float lo = lo0;

#pragma unroll 1
                for (int it = 0; it < MAX_ITER; it++) {
                    const float diff = f_lo - f_hi;
                    if (diff * diff < TOL) break;
                    const float tau = (lo * f_hi - hi * f_lo) / (f_hi - f_lo);
                    if (!(tau >= max_val)) { fb = 1; break; }  // left overshoot / NaN
                    lo = hi;
                    f_lo = f_hi;
                    hi = tau;
                    // eval over compacted set (valid: tau >= max_val)
                    const float c2 = fmaf(tau, -0.5f, 1.0f);
                    float a0 = 0.0f, a1 = 0.0f;
                    for (int i = lane; i < n_act; i += 64) {
                        float v = fmaxf(fmaf(act[i], 0.5f, c2), 0.0f);
                        a0 = fmaf(v, v, a0);
                        int j = i + 32;
                        if (j < n_act) {
                            float w = fmaxf(fmaf(act[j], 0.5f, c2), 0.0f);
                            a1 = fmaf(w, w, a1);
                        }
                    }
                    f_hi = warp_sum(a0 + a1) - 1.0f;
                }
            } else {
                fb = 1;
            }
            if (lane == 0) { tau_s = hi; fb_s = fb; }
        }
        __syncthreads();

        float tau_final;
        if (fb_s) {
            // ---- exact full-register block secant (rare, deterministic) ----
            auto part_full = [&](float c2) -> float {
                float a0 = 0.f, a1 = 0.f, a2 = 0.f, a3 = 0.f;
#pragma unroll
                for (int k = 0; k < NE; k += 4) {
                    float v0 = fmaxf(fmaf(xv[k + 0], 0.5f, c2), 0.0f);
                    float v1 = fmaxf(fmaf(xv[k + 1], 0.5f, c2), 0.0f);
                    float v2 = fmaxf(fmaf(xv[k + 2], 0.5f, c2), 0.0f);
                    float v3 = fmaxf(fmaf(xv[k + 3], 0.5f, c2), 0.0f);
                    a0 = fmaf(v0, v0, a0);
                    a1 = fmaf(v1, v1, a1);
                    a2 = fmaf(v2, v2, a2);
                    a3 = fmaf(v3, v3, a3);
                }
                return (a0 + a1) + (a2 + a3);
            };
            float lo = lo0, hi = hi0;
            float f_lo = block_sum(part_full(fmaf(lo, -0.5f, 1.0f))) - 1.0f;
            float f_hi = block_sum(part_full(fmaf(hi, -0.5f, 1.0f))) - 1.0f;
#pragma unroll 1
            for (int it = 0; it < MAX_ITER; it++) {
                const float diff = f_lo - f_hi;
                if (diff * diff < TOL) break;
                const float tau = (lo * f_hi - hi * f_lo) / (f_hi - f_lo);
                lo = hi;
                f_lo = f_hi;
                hi = tau;
                f_hi = block_sum(part_full(fmaf(tau, -0.5f, 1.0f))) - 1.0f;
            }
            tau_final = hi;
        } else {
            tau_final = tau_s;
        }

        // ---- write p(X - tau_final) with streaming stores ----
        float4* y4 = reinterpret_cast<float4*>(Y) + (size_t)row * D4;
        const float c2 = fmaf(tau_final, -0.5f, 1.0f);
#pragma unroll
        for (int k = 0; k < NV4; k++) {
            const int i4 = tid + k * THREADS;
            if (k < NV4 - 1 || i4 < D4) {
                float v0 = fmaxf(fmaf(xv[4 * k + 0], 0.5f, c2), 0.0f);
                float v1 = fmaxf(fmaf(xv[4 * k + 1], 0.5f, c2), 0.0f);
                float v2 = fmaxf(fmaf(xv[4 * k + 2], 0.5f, c2), 0.0f);
                float v3 = fmaxf(fmaf(xv[4 * k + 3], 0.5f, c2), 0.0f);
                float4 r;
                r.x = v0 * v0;
                r.y = v1 * v1;
                r.z = v2 * v2;
                r.w = v3 * v3;
                __stcs(&y4[i4], r);
            }
        }
        __syncthreads();   // act/red/iscan reuse fence before next row
    }
}

extern "C" void kernel_launch(void* const* d_in, const int* in_sizes, int n_in,
                              void* d_out, int out_size) {
    const float* X = (const float*)d_in[0];
    float* Y = (float*)d_out;

    static int n_sm = 0;
    if (n_sm == 0) {
        cudaDeviceGetAttribute(&n_sm, cudaDevAttrMultiProcessorCount, 0);
        cudaFuncSetAttribute(tsallis_secant_kernel,
                             cudaFuncAttributeMaxDynamicSharedMemorySize,
                             ROW_BYTES);
    }
    tsallis_secant_kernel<<<n_sm, THREADS, ROW_BYTES>>>(X, Y);
}